// round 8
// baseline (speedup 1.0000x reference)
#include <cuda_runtime.h>

#define BATCH      16384
#define FIELD_DIM  100000
#define THREADS    128
#define WARPS      4
#define RPW        4
#define NBLOCKS    (BATCH / (WARPS * RPW))   // 1024
#define PAD        66                        // stride (floats) for transposed W rows

__global__ __launch_bounds__(THREADS) void fused_kernel(
    const int*   __restrict__ x,    // [B, 26]
    const float* __restrict__ t0,   // [800000, 64]
    const float* __restrict__ t1,   // [800000, 32]
    const float* __restrict__ t2,   // [1000000, 16]
    const float* __restrict__ W1,   // [64, 32]
    const float* __restrict__ b1,   // [64]
    const float* __restrict__ W2,   // [64, 16]
    const float* __restrict__ b2,   // [64]
    float*       __restrict__ out)  // [B, 64]
{
    // Transposed W, pad-66 rows: sW1f[k*PAD + o] = W1[o][k]
    __shared__ float sW1f[32 * PAD];
    __shared__ float sW2f[16 * PAD];
    __shared__ float sBiasF[64];
    __shared__ float sS[WARPS][RPW][48];

    const int tid  = threadIdx.x;
    const int warp = tid >> 5;
    const int lane = tid & 31;
    const unsigned FULL = 0xffffffffu;

    // ---- stage W: coalesced LDG, transposed STS ----
    #pragma unroll
    for (int i = tid; i < 64 * 32; i += THREADS) {
        int o = i >> 5, k = i & 31;
        sW1f[k * PAD + o] = W1[i];
    }
    #pragma unroll
    for (int i = tid; i < 64 * 16; i += THREADS) {
        int o = i >> 4, k = i & 15;
        sW2f[k * PAD + o] = W2[i];
    }
    if (tid < 64) sBiasF[tid] = 8.f * b1[tid] + 10.f * b2[tid];
    __syncthreads();

    const int row0 = (blockIdx.x * WARPS + warp) * RPW;
    const float2 bias = *(const float2*)&sBiasF[2 * lane];
    const int half = lane >> 4;
    const int l16  = lane & 15;

    float2 acc[RPW];

    // ---- phase 1: gather + segment-sum, RPW rows ----
    #pragma unroll
    for (int r = 0; r < RPW; r++) {
        const int row = row0 + r;
        int myidx = 0;
        if (lane < 26) myidx = x[row * 26 + lane];

        // block 0: 8 fields, 256B coalesced rows
        float2 v0[8];
        #pragma unroll
        for (int f = 0; f < 8; f++) {
            unsigned idx = (unsigned)__shfl_sync(FULL, myidx, f) + (unsigned)(f * FIELD_DIM);
            v0[f] = ((const float2*)t0)[idx * 32u + lane];
        }
        // block 1: 8 fields, 128B coalesced rows
        float v1[8];
        #pragma unroll
        for (int f = 0; f < 8; f++) {
            unsigned idx = (unsigned)__shfl_sync(FULL, myidx, 8 + f) + (unsigned)(f * FIELD_DIM);
            v1[f] = t1[idx * 32u + lane];
        }
        // block 2: 10 fields, 64B rows, two per warp-load
        float v2[5];
        #pragma unroll
        for (int p = 0; p < 5; p++) {
            int f = 2 * p + half;
            unsigned idx = (unsigned)__shfl_sync(FULL, myidx, 16 + f) + (unsigned)f * FIELD_DIM;
            v2[p] = t2[idx * 16u + l16];
        }

        float2 a = bias;
        #pragma unroll
        for (int f = 0; f < 8; f++) { a.x += v0[f].x; a.y += v0[f].y; }
        acc[r] = a;

        float s1 = 0.f;
        #pragma unroll
        for (int f = 0; f < 8; f++) s1 += v1[f];

        float s2 = 0.f;
        #pragma unroll
        for (int p = 0; p < 5; p++) s2 += v2[p];
        s2 += __shfl_xor_sync(FULL, s2, 16);

        sS[warp][r][lane] = s1;
        if (lane < 16) sS[warp][r][32 + lane] = s2;
    }
    __syncwarp();

    // ---- phase 2: projection, W-LDS amortized over RPW rows ----
    #pragma unroll
    for (int k4 = 0; k4 < 12; k4++) {
        float4 s4[RPW];
        #pragma unroll
        for (int r = 0; r < RPW; r++)
            s4[r] = *(const float4*)&sS[warp][r][k4 * 4];   // uniform bcast

        #pragma unroll
        for (int j = 0; j < 4; j++) {
            const int k = k4 * 4 + j;                       // compile-time
            float2 w;
            if (k < 32) w = *(const float2*)&sW1f[k * PAD + 2 * lane];
            else        w = *(const float2*)&sW2f[(k - 32) * PAD + 2 * lane];
            #pragma unroll
            for (int r = 0; r < RPW; r++) {
                float sv = (j == 0) ? s4[r].x : (j == 1) ? s4[r].y
                         : (j == 2) ? s4[r].z : s4[r].w;
                acc[r].x += w.x * sv;
                acc[r].y += w.y * sv;
            }
        }
    }

    // ---- coalesced stores ----
    #pragma unroll
    for (int r = 0; r < RPW; r++)
        ((float2*)(out + (long long)(row0 + r) * 64))[lane] = acc[r];
}

extern "C" void kernel_launch(void* const* d_in, const int* in_sizes, int n_in,
                              void* d_out, int out_size)
{
    const int*   x  = (const int*)  d_in[0];
    const float* t0 = (const float*)d_in[1];
    const float* t1 = (const float*)d_in[2];
    const float* t2 = (const float*)d_in[3];
    const float* W1 = (const float*)d_in[4];
    const float* b1 = (const float*)d_in[5];
    const float* W2 = (const float*)d_in[6];
    const float* b2 = (const float*)d_in[7];
    float* out = (float*)d_out;

    fused_kernel<<<NBLOCKS, THREADS>>>(x, t0, t1, t2, W1, b1, W2, b2, out);
}

// round 9
// speedup vs baseline: 1.0194x; 1.0194x over previous
#include <cuda_runtime.h>

#define BATCH      16384
#define FIELD_DIM  100000
#define THREADS    256
#define WARPS      8
#define RPW        2
#define NBLOCKS    (BATCH / (WARPS * RPW))   // 1024
#define PAD        66                        // stride (floats) for transposed W rows

__global__ __launch_bounds__(THREADS, 4) void fused_kernel(
    const int*   __restrict__ x,    // [B, 26]
    const float* __restrict__ t0,   // [800000, 64]
    const float* __restrict__ t1,   // [800000, 32]
    const float* __restrict__ t2,   // [1000000, 16]
    const float* __restrict__ W1,   // [64, 32]
    const float* __restrict__ b1,   // [64]
    const float* __restrict__ W2,   // [64, 16]
    const float* __restrict__ b2,   // [64]
    float*       __restrict__ out)  // [B, 64]
{
    // Transposed W, pad-66 rows: sW1f[k*PAD + o] = W1[o][k]
    __shared__ float sW1f[32 * PAD];
    __shared__ float sW2f[16 * PAD];
    __shared__ float sBiasF[64];
    __shared__ float sS[WARPS][RPW][48];

    const int tid  = threadIdx.x;
    const int warp = tid >> 5;
    const int lane = tid & 31;
    const unsigned FULL = 0xffffffffu;

    // ---- stage W: coalesced LDG, transposed STS (2-way conflicts max) ----
    #pragma unroll
    for (int i = tid; i < 64 * 32; i += THREADS) {
        int o = i >> 5, k = i & 31;
        sW1f[k * PAD + o] = W1[i];
    }
    #pragma unroll
    for (int i = tid; i < 64 * 16; i += THREADS) {
        int o = i >> 4, k = i & 15;
        sW2f[k * PAD + o] = W2[i];
    }
    if (tid < 64) sBiasF[tid] = 8.f * b1[tid] + 10.f * b2[tid];
    __syncthreads();

    const int row0 = (blockIdx.x * WARPS + warp) * RPW;

    // ---- load indices for both rows ----
    int i0 = 0, i1 = 0;
    if (lane < 26) {
        i0 = x[(row0 + 0) * 26 + lane];
        i1 = x[(row0 + 1) * 26 + lane];
    }

    // ---- issue ALL gathers for both rows back-to-back (max MLP) ----
    float2 v0a[8], v0b[8];
    #pragma unroll
    for (int f = 0; f < 8; f++) {
        unsigned ia = (unsigned)__shfl_sync(FULL, i0, f) + (unsigned)(f * FIELD_DIM);
        unsigned ib = (unsigned)__shfl_sync(FULL, i1, f) + (unsigned)(f * FIELD_DIM);
        v0a[f] = ((const float2*)t0)[ia * 32u + lane];
        v0b[f] = ((const float2*)t0)[ib * 32u + lane];
    }
    float v1a[8], v1b[8];
    #pragma unroll
    for (int f = 0; f < 8; f++) {
        unsigned ia = (unsigned)__shfl_sync(FULL, i0, 8 + f) + (unsigned)(f * FIELD_DIM);
        unsigned ib = (unsigned)__shfl_sync(FULL, i1, 8 + f) + (unsigned)(f * FIELD_DIM);
        v1a[f] = t1[ia * 32u + lane];
        v1b[f] = t1[ib * 32u + lane];
    }
    const int half = lane >> 4;
    const int l16  = lane & 15;
    float v2a[5], v2b[5];
    #pragma unroll
    for (int p = 0; p < 5; p++) {
        int f = 2 * p + half;
        unsigned ia = (unsigned)__shfl_sync(FULL, i0, 16 + f) + (unsigned)f * FIELD_DIM;
        unsigned ib = (unsigned)__shfl_sync(FULL, i1, 16 + f) + (unsigned)f * FIELD_DIM;
        v2a[p] = t2[ia * 16u + l16];
        v2b[p] = t2[ib * 16u + l16];
    }

    // ---- reductions ----
    const float2 bias = *(const float2*)&sBiasF[2 * lane];
    float2 acc0 = bias, acc1 = bias;
    #pragma unroll
    for (int f = 0; f < 8; f++) {
        acc0.x += v0a[f].x; acc0.y += v0a[f].y;
        acc1.x += v0b[f].x; acc1.y += v0b[f].y;
    }

    float s1a = 0.f, s1b = 0.f;
    #pragma unroll
    for (int f = 0; f < 8; f++) { s1a += v1a[f]; s1b += v1b[f]; }

    float s2a = 0.f, s2b = 0.f;
    #pragma unroll
    for (int p = 0; p < 5; p++) { s2a += v2a[p]; s2b += v2b[p]; }
    s2a += __shfl_xor_sync(FULL, s2a, 16);
    s2b += __shfl_xor_sync(FULL, s2b, 16);

    // ---- stage block-sums for uniform broadcast ----
    sS[warp][0][lane] = s1a;
    sS[warp][1][lane] = s1b;
    if (lane < 16) {
        sS[warp][0][32 + lane] = s2a;
        sS[warp][1][32 + lane] = s2b;
    }
    __syncwarp();

    // ---- projection: 48 k-steps, W-LDS amortized over 2 rows ----
    #pragma unroll
    for (int k4 = 0; k4 < 12; k4++) {
        float4 sa = *(const float4*)&sS[warp][0][k4 * 4];   // uniform bcast
        float4 sb = *(const float4*)&sS[warp][1][k4 * 4];
        #pragma unroll
        for (int j = 0; j < 4; j++) {
            const int k = k4 * 4 + j;                       // compile-time
            float2 w;
            if (k < 32) w = *(const float2*)&sW1f[k * PAD + 2 * lane];
            else        w = *(const float2*)&sW2f[(k - 32) * PAD + 2 * lane];
            float va = (j == 0) ? sa.x : (j == 1) ? sa.y : (j == 2) ? sa.z : sa.w;
            float vb = (j == 0) ? sb.x : (j == 1) ? sb.y : (j == 2) ? sb.z : sb.w;
            acc0.x += w.x * va; acc0.y += w.y * va;
            acc1.x += w.x * vb; acc1.y += w.y * vb;
        }
    }

    // ---- single coalesced store per row ----
    ((float2*)(out + (long long)(row0 + 0) * 64))[lane] = acc0;
    ((float2*)(out + (long long)(row0 + 1) * 64))[lane] = acc1;
}

extern "C" void kernel_launch(void* const* d_in, const int* in_sizes, int n_in,
                              void* d_out, int out_size)
{
    const int*   x  = (const int*)  d_in[0];
    const float* t0 = (const float*)d_in[1];
    const float* t1 = (const float*)d_in[2];
    const float* t2 = (const float*)d_in[3];
    const float* W1 = (const float*)d_in[4];
    const float* b1 = (const float*)d_in[5];
    const float* W2 = (const float*)d_in[6];
    const float* b2 = (const float*)d_in[7];
    float* out = (float*)d_out;

    fused_kernel<<<NBLOCKS, THREADS>>>(x, t0, t1, t2, W1, b1, W2, b2, out);
}